// round 8
// baseline (speedup 1.0000x reference)
#include <cuda_runtime.h>
#include <cstdint>
#include <cstddef>

#define Bsz 128
#define Tt  2048
#define Cin 16
#define CO  128
#define Hh  128
#define Gg  512

// -------- scratch (no allocations allowed; __device__ globals are the sanctioned path) ------
__device__ float g_seq[(size_t)Bsz * Tt * CO];      // conv output, [b*T+t][co]
__device__ float g_x0 [(size_t)Bsz * Tt * Gg];      // layer-0 input projection, [b*T+t][g]
__device__ float g_pooled[Bsz * Hh];                // mean over t of h1

// ---------------- packed f32x2 helpers ----------------
__device__ __forceinline__ unsigned long long fma2(unsigned long long a, unsigned long long b,
                                                   unsigned long long c) {
    unsigned long long d;
    asm("fma.rn.f32x2 %0, %1, %2, %3;" : "=l"(d) : "l"(a), "l"(b), "l"(c));
    return d;
}
__device__ __forceinline__ unsigned long long pack2(float lo, float hi) {
    unsigned long long r;
    asm("mov.b64 %0, {%1, %2};" : "=l"(r) : "f"(lo), "f"(hi));
    return r;
}
__device__ __forceinline__ void unpack2(unsigned long long v, float& a, float& b) {
    asm("mov.b64 {%0, %1}, %2;" : "=f"(a), "=f"(b) : "l"(v));
}
__device__ __forceinline__ float sum2(unsigned long long v) {
    float a, b; unpack2(v, a, b); return a + b;
}

// ============================ kernel 1: conv1d(k=3,pad=1) + LeakyReLU ============================
__global__ void conv_kernel(const float* __restrict__ x, const float* __restrict__ cw,
                            const float* __restrict__ cb) {
    __shared__ float xs[130 * 16];     // t0-1 .. t0+128
    __shared__ float wct[48 * 128];    // [(c*3+kk)][co]
    __shared__ float cbs[128];
    int tid = threadIdx.x;
    int b = blockIdx.y, t0 = blockIdx.x * 128;
    for (int i = tid; i < 130 * 16; i += 256) {
        int row = i >> 4, c = i & 15;
        int t = t0 - 1 + row;
        xs[i] = (t >= 0 && t < Tt) ? x[((size_t)b * Tt + t) * Cin + c] : 0.0f;
    }
    for (int i = tid; i < 48 * 128; i += 256) {
        int co = i / 48, rem = i % 48;          // rem = c*3 + kk
        wct[rem * 128 + co] = cw[i];
    }
    if (tid < 128) cbs[tid] = cb[tid];
    __syncthreads();
    for (int idx = tid; idx < 128 * 128; idx += 256) {
        int tl = idx >> 7, co = idx & 127;
        float acc = cbs[co];
#pragma unroll
        for (int c = 0; c < 16; c++)
#pragma unroll
            for (int kk = 0; kk < 3; kk++)
                acc += xs[(tl + kk) * 16 + c] * wct[(c * 3 + kk) * 128 + co];
        acc = acc >= 0.f ? acc : 0.01f * acc;
        g_seq[((size_t)b * Tt + t0 + tl) * CO + co] = acc;
    }
}

// ============================ kernel 2: x0 = seq @ w_ih0^T + (b_ih0+b_hh0) ============================
#define PROJ_SMEM_BYTES ((128 * 132 + 128 * 64) * 4)
__global__ void proj_kernel(const float* __restrict__ w, const float* __restrict__ bi,
                            const float* __restrict__ bh) {
    extern __shared__ float sm[];
    float* As = sm;                 // [128][132] (padded)
    float* Ws = sm + 128 * 132;     // [k=128][n=64]
    int tid = threadIdx.x;
    int mt = blockIdx.x, nt = blockIdx.y;
    const float* Ab = g_seq + (size_t)mt * 128 * CO;
    for (int i = tid; i < 128 * 32; i += 256) {
        int row = i >> 5, c4 = i & 31;
        float4 v = reinterpret_cast<const float4*>(Ab)[(size_t)row * 32 + c4];
        float* d = As + row * 132 + c4 * 4;
        d[0] = v.x; d[1] = v.y; d[2] = v.z; d[3] = v.w;
    }
    for (int i = tid; i < 64 * 128; i += 256) {
        int n = i >> 7, k = i & 127;
        Ws[k * 64 + n] = w[(size_t)(nt * 64 + n) * CO + k];
    }
    __syncthreads();
    int ty = tid >> 4, tx = tid & 15;
    unsigned long long acc2[8][2];
#pragma unroll
    for (int i = 0; i < 8; i++) { acc2[i][0] = 0ull; acc2[i][1] = 0ull; }
#pragma unroll 2
    for (int k0 = 0; k0 < 128; k0 += 4) {
        float4 av[8];
#pragma unroll
        for (int m = 0; m < 8; m++)
            av[m] = *reinterpret_cast<const float4*>(As + (ty * 8 + m) * 132 + k0);
#pragma unroll
        for (int kk = 0; kk < 4; kk++) {
            ulonglong2 w2 = *reinterpret_cast<const ulonglong2*>(Ws + (k0 + kk) * 64 + tx * 4);
#pragma unroll
            for (int m = 0; m < 8; m++) {
                float a = (kk == 0) ? av[m].x : (kk == 1) ? av[m].y : (kk == 2) ? av[m].z : av[m].w;
                unsigned long long a2 = pack2(a, a);
                acc2[m][0] = fma2(a2, w2.x, acc2[m][0]);
                acc2[m][1] = fma2(a2, w2.y, acc2[m][1]);
            }
        }
    }
    int n0 = nt * 64 + tx * 4;
    float bb0 = bi[n0] + bh[n0], bb1 = bi[n0 + 1] + bh[n0 + 1];
    float bb2 = bi[n0 + 2] + bh[n0 + 2], bb3 = bi[n0 + 3] + bh[n0 + 3];
#pragma unroll
    for (int i = 0; i < 8; i++) {
        float4 o;
        unpack2(acc2[i][0], o.x, o.y);
        unpack2(acc2[i][1], o.z, o.w);
        o.x += bb0; o.y += bb1; o.z += bb2; o.w += bb3;
        *reinterpret_cast<float4*>(g_x0 + ((size_t)mt * 128 + ty * 8 + i) * Gg + n0) = o;
    }
}

// ============================ kernel 3: persistent 2-layer LSTM, cluster-of-4 ============================
// 32 clusters x 4 CTAs, 256 threads/CTA. Cluster owns 4 batch rows.
// CTA r owns gate rows {g*128 + r*32 + j}; threads split k in half.
// W_hh0 half-rows in REGISTERS (32 regs/thread); W_ih1/W_hh1 in smem.
// Cross-CTA h exchange via st.shared::cluster; per-step sync via mbarrier
// (4 release-arrivals per barrier per phase) instead of barrier.cluster.
// x0 prefetched 2 steps deep.

__device__ __forceinline__ float tanh_fast(float x) {
    float y; asm("tanh.approx.f32 %0, %1;" : "=f"(y) : "f"(x)); return y;
}
__device__ __forceinline__ float sig_fast(float x) {
    return fmaf(tanh_fast(0.5f * x), 0.5f, 0.5f);
}

// acc2[bb] += sum_k w[k] * hb[bb*128 + k] over a 64-float k-half (weights in registers)
__device__ __forceinline__ void gemm_regw(const ulonglong2 wreg[16],
                                          const float* __restrict__ hb,
                                          unsigned long long acc2[4]) {
#pragma unroll
    for (int kq = 0; kq < 16; kq++) {
        ulonglong2 wv = wreg[kq];
#pragma unroll
        for (int bb = 0; bb < 4; bb++) {
            ulonglong2 hv = reinterpret_cast<const ulonglong2*>(hb + bb * 128)[kq];
            acc2[bb] = fma2(wv.x, hv.x, acc2[bb]);
            acc2[bb] = fma2(wv.y, hv.y, acc2[bb]);
        }
    }
}

// same but weights from smem
__device__ __forceinline__ void gemm_smem(const float* __restrict__ wrow,
                                          const float* __restrict__ hb,
                                          unsigned long long acc2[4]) {
    const ulonglong2* wp = reinterpret_cast<const ulonglong2*>(wrow);
#pragma unroll
    for (int kq = 0; kq < 16; kq++) {
        ulonglong2 wv = wp[kq];
#pragma unroll
        for (int bb = 0; bb < 4; bb++) {
            ulonglong2 hv = reinterpret_cast<const ulonglong2*>(hb + bb * 128)[kq];
            acc2[bb] = fma2(wv.x, hv.x, acc2[bb]);
            acc2[bb] = fma2(wv.y, hv.y, acc2[bb]);
        }
    }
}

#define LSTM_SMEM_BYTES (2 * 128 * 132 * 4)

__global__ void __cluster_dims__(4, 1, 1) __launch_bounds__(256, 1)
lstm_kernel(const float* __restrict__ whh0, const float* __restrict__ wih1,
            const float* __restrict__ whh1, const float* __restrict__ bih1,
            const float* __restrict__ bhh1) {
    extern __shared__ float smw[];          // W_ih1, W_hh1 slices [128][132] each
    float* w1 = smw;
    float* w2 = smw + 128 * 132;
    __shared__ float hbuf[2048];            // [2 p][2 layer][4 bb][128 k]
    __shared__ float gtmp[2048];            // [2 layer][4 bb][2 half][128 row]
    __shared__ __align__(8) unsigned long long mbar[1];

    int tid = threadIdx.x;
    int half = tid >> 7;                    // k-half for GEMM; cell index for elementwise
    int wt = tid & 127, q = wt >> 5, j = wt & 31;
    uint32_t rank; asm("mov.u32 %0, %%cluster_ctarank;" : "=r"(rank));
    int r = (int)rank;
    int b0 = (blockIdx.x >> 2) * 4;
    int lr = wt;                            // local row
    int rowg = (q << 7) + (r << 5) + j;     // global gate row of this CTA's slice

    // ---- W_hh0 half-row into registers ----
    ulonglong2 w0r[16];
    {
        const ulonglong2* p0 =
            reinterpret_cast<const ulonglong2*>(whh0 + (size_t)rowg * Hh + half * 64);
#pragma unroll
        for (int kq = 0; kq < 16; kq++) w0r[kq] = p0[kq];
    }
    // ---- W_ih1 / W_hh1 slices into smem ----
    for (int i = tid; i < 128 * 128; i += 256) {
        int rl = i >> 7, k = i & 127;
        int rg = ((rl >> 5) << 7) + (r << 5) + (rl & 31);
        w1[rl * 132 + k] = wih1[(size_t)rg * Hh + k];
        w2[rl * 132 + k] = whh1[(size_t)rg * Hh + k];
    }
    for (int i = tid; i < 2048; i += 256) hbuf[i] = 0.f;

    float b1init = (half == 0) ? (bih1[rowg] + bhh1[rowg]) : 0.f;

    int hl = (r << 5) + j;                  // owned h index (elementwise role, batch=q, cell=half)
    float cst = 0.f, pool = 0.f;

    // x0 prefetch pipeline: xn = t, xnn = t+1
    float xn[4], xnn[4];
    if (half == 0) {
#pragma unroll
        for (int bb = 0; bb < 4; bb++) {
            xn [bb] = g_x0[((size_t)(b0 + bb) * Tt + 0) * Gg + rowg];
            xnn[bb] = g_x0[((size_t)(b0 + bb) * Tt + 1) * Gg + rowg];
        }
    }

    // DSMEM addresses: hbuf bases + mbar bases on all 4 ranks
    uint32_t hb_la = (uint32_t)__cvta_generic_to_shared(hbuf);
    uint32_t mb_la = (uint32_t)__cvta_generic_to_shared(mbar);
    uint32_t rb[4];
#pragma unroll
    for (int rk = 0; rk < 4; rk++)
        asm("mapa.shared::cluster.u32 %0, %1, %2;" : "=r"(rb[rk]) : "r"(hb_la), "r"(rk));
    uint32_t mb_rem = 0;
    if (tid < 4)
        asm("mapa.shared::cluster.u32 %0, %1, %2;" : "=r"(mb_rem) : "r"(mb_la), "r"(tid));

    if (tid == 0)
        asm volatile("mbarrier.init.shared.b64 [%0], 4;" :: "r"(mb_la) : "memory");
    __syncthreads();
    asm volatile("barrier.cluster.arrive.aligned;" ::: "memory");
    asm volatile("barrier.cluster.wait.aligned;"   ::: "memory");

    const float* wr1 = w1 + lr * 132 + half * 64;
    const float* wr2 = w2 + lr * 132 + half * 64;

    int p = 0;
    for (int t = 0; t <= Tt; t++) {
        const float* hcur = hbuf + p * 1024 + half * 64;   // layer0 h base (+512 -> layer1 h)
        // ---- GEMM A: gates0(t) = x0[t] + W_hh0 . h0   (register weights; skip on last iter)
        if (t < Tt) {
            unsigned long long acc2[4];
#pragma unroll
            for (int bb = 0; bb < 4; bb++) acc2[bb] = pack2(half == 0 ? xn[bb] : 0.f, 0.f);
            gemm_regw(w0r, hcur, acc2);
#pragma unroll
            for (int bb = 0; bb < 4; bb++)
                gtmp[((0 + bb) * 2 + half) * 128 + lr] = sum2(acc2[bb]);
        }
        // ---- GEMM B: gates1 = b1 + W_ih1 . h0 + W_hh1 . h1   (skip on first iter)
        if (t > 0) {
            unsigned long long acc2[4];
#pragma unroll
            for (int bb = 0; bb < 4; bb++) acc2[bb] = pack2(b1init, 0.f);
            gemm_smem(wr1, hcur, acc2);
            gemm_smem(wr2, hcur + 512, acc2);
#pragma unroll
            for (int bb = 0; bb < 4; bb++)
                gtmp[((4 + bb) * 2 + half) * 128 + lr] = sum2(acc2[bb]);
        }
        __syncthreads();
        // ---- elementwise: thread owns (cell=half, batch=q, h=hl)
        bool act = (half == 0) ? (t < Tt) : (t > 0);
        if (act) {
            int gb = (half * 4 + q) * 256;
            float gv[4];
#pragma unroll
            for (int g = 0; g < 4; g++)
                gv[g] = gtmp[gb + (g << 5) + j] + gtmp[gb + 128 + (g << 5) + j];
            float cn = sig_fast(gv[1]) * cst + sig_fast(gv[0]) * tanh_fast(gv[2]);
            float hn = sig_fast(gv[3]) * tanh_fast(cn);
            cst = cn;
            if (half) pool += hn;
            uint32_t off = (uint32_t)((((p ^ 1) << 10) + (half << 9) + (q << 7) + hl) << 2);
#pragma unroll
            for (int rk = 0; rk < 4; rk++)
                asm volatile("st.shared::cluster.f32 [%0], %1;"
                             :: "r"(rb[rk] + off), "f"(hn) : "memory");
        }
        __syncthreads();   // all CTA stores done before the elected release-arrives
        if (tid < 4)
            asm volatile("mbarrier.arrive.release.cluster.shared::cluster.b64 _, [%0];"
                         :: "r"(mb_rem) : "memory");
        // rotate x0 pipeline and prefetch t+2 while peers arrive
        if (half == 0) {
#pragma unroll
            for (int bb = 0; bb < 4; bb++) xn[bb] = xnn[bb];
            if (t + 2 < Tt) {
#pragma unroll
                for (int bb = 0; bb < 4; bb++)
                    xnn[bb] = g_x0[((size_t)(b0 + bb) * Tt + (t + 2)) * Gg + rowg];
            }
        }
        // wait for all 4 CTAs' arrivals for this phase
        {
            uint32_t par = (uint32_t)(t & 1);
            uint32_t done;
            asm volatile(
                "{\n\t.reg .pred P;\n\t"
                "mbarrier.try_wait.parity.acquire.cluster.shared::cta.b64 P, [%1], %2;\n\t"
                "selp.b32 %0, 1, 0, P;\n\t}"
                : "=r"(done) : "r"(mb_la), "r"(par) : "memory");
            if (!done) {
                asm volatile(
                    "{\n\t.reg .pred P;\n\t"
                    "WL_%=:\n\t"
                    "mbarrier.try_wait.parity.acquire.cluster.shared::cta.b64 P, [%0], %1, 0x989680;\n\t"
                    "@P bra.uni WD_%=;\n\t"
                    "bra.uni WL_%=;\n\t"
                    "WD_%=:\n\t}"
                    :: "r"(mb_la), "r"(par) : "memory");
            }
        }
        p ^= 1;
    }
    if (half == 1)
        g_pooled[(size_t)(b0 + q) * Hh + hl] = pool * (1.0f / 2048.0f);
    // keep CTAs resident until every peer is past its last remote store
    asm volatile("barrier.cluster.arrive.aligned;" ::: "memory");
    asm volatile("barrier.cluster.wait.aligned;"   ::: "memory");
}

// ============================ kernel 4: out[b] = pooled[b,:] . lin_w + lin_b ============================
__global__ void final_kernel(const float* __restrict__ lw, const float* __restrict__ lb,
                             float* __restrict__ out) {
    int b = threadIdx.x;
    float acc = lb[0];
#pragma unroll 8
    for (int h = 0; h < Hh; h++) acc += g_pooled[b * Hh + h] * lw[h];
    out[b] = acc;
}

// ============================ launch ============================
extern "C" void kernel_launch(void* const* d_in, const int* in_sizes, int n_in,
                              void* d_out, int out_size) {
    (void)in_sizes; (void)n_in; (void)out_size;
    const float* x      = (const float*)d_in[0];
    const float* conv_w = (const float*)d_in[1];
    const float* conv_b = (const float*)d_in[2];
    const float* w_ih0  = (const float*)d_in[3];
    const float* w_hh0  = (const float*)d_in[4];
    const float* b_ih0  = (const float*)d_in[5];
    const float* b_hh0  = (const float*)d_in[6];
    const float* w_ih1  = (const float*)d_in[7];
    const float* w_hh1  = (const float*)d_in[8];
    const float* b_ih1  = (const float*)d_in[9];
    const float* b_hh1  = (const float*)d_in[10];
    const float* lin_w  = (const float*)d_in[11];
    const float* lin_b  = (const float*)d_in[12];
    float* out = (float*)d_out;

    cudaFuncSetAttribute(proj_kernel, cudaFuncAttributeMaxDynamicSharedMemorySize, PROJ_SMEM_BYTES);
    cudaFuncSetAttribute(lstm_kernel, cudaFuncAttributeMaxDynamicSharedMemorySize, LSTM_SMEM_BYTES);

    conv_kernel<<<dim3(Tt / 128, Bsz), 256>>>(x, conv_w, conv_b);
    proj_kernel<<<dim3((Bsz * Tt) / 128, Gg / 64), 256, PROJ_SMEM_BYTES>>>(w_ih0, b_ih0, b_hh0);
    lstm_kernel<<<128, 256, LSTM_SMEM_BYTES>>>(w_hh0, w_ih1, w_hh1, b_ih1, b_hh1);
    final_kernel<<<1, 128>>>(lin_w, lin_b, out);
}

// round 9
// speedup vs baseline: 4.0933x; 4.0933x over previous
#include <cuda_runtime.h>
#include <cstdint>
#include <cstddef>

#define Bsz 128
#define Tt  2048
#define Cin 16
#define CO  128
#define Hh  128
#define Gg  512

// -------- scratch (no allocations allowed; __device__ globals are the sanctioned path) ------
__device__ float g_seq[(size_t)Bsz * Tt * CO];      // conv output, [b*T+t][co]
__device__ float g_x0 [(size_t)Bsz * Tt * Gg];      // layer-0 input projection, [b*T+t][g]
__device__ float g_pooled[Bsz * Hh];                // mean over t of h1

// ---------------- packed f32x2 helpers ----------------
__device__ __forceinline__ unsigned long long fma2(unsigned long long a, unsigned long long b,
                                                   unsigned long long c) {
    unsigned long long d;
    asm("fma.rn.f32x2 %0, %1, %2, %3;" : "=l"(d) : "l"(a), "l"(b), "l"(c));
    return d;
}
__device__ __forceinline__ unsigned long long pack2(float lo, float hi) {
    unsigned long long r;
    asm("mov.b64 %0, {%1, %2};" : "=l"(r) : "f"(lo), "f"(hi));
    return r;
}
__device__ __forceinline__ void unpack2(unsigned long long v, float& a, float& b) {
    asm("mov.b64 {%0, %1}, %2;" : "=f"(a), "=f"(b) : "l"(v));
}
__device__ __forceinline__ float sum2(unsigned long long v) {
    float a, b; unpack2(v, a, b); return a + b;
}

// ============================ kernel 1: conv1d(k=3,pad=1) + LeakyReLU ============================
__global__ void conv_kernel(const float* __restrict__ x, const float* __restrict__ cw,
                            const float* __restrict__ cb) {
    __shared__ float xs[130 * 16];     // t0-1 .. t0+128
    __shared__ float wct[48 * 128];    // [(c*3+kk)][co]
    __shared__ float cbs[128];
    int tid = threadIdx.x;
    int b = blockIdx.y, t0 = blockIdx.x * 128;
    for (int i = tid; i < 130 * 16; i += 256) {
        int row = i >> 4, c = i & 15;
        int t = t0 - 1 + row;
        xs[i] = (t >= 0 && t < Tt) ? x[((size_t)b * Tt + t) * Cin + c] : 0.0f;
    }
    for (int i = tid; i < 48 * 128; i += 256) {
        int co = i / 48, rem = i % 48;          // rem = c*3 + kk
        wct[rem * 128 + co] = cw[i];
    }
    if (tid < 128) cbs[tid] = cb[tid];
    __syncthreads();
    for (int idx = tid; idx < 128 * 128; idx += 256) {
        int tl = idx >> 7, co = idx & 127;
        float acc = cbs[co];
#pragma unroll
        for (int c = 0; c < 16; c++)
#pragma unroll
            for (int kk = 0; kk < 3; kk++)
                acc += xs[(tl + kk) * 16 + c] * wct[(c * 3 + kk) * 128 + co];
        acc = acc >= 0.f ? acc : 0.01f * acc;
        g_seq[((size_t)b * Tt + t0 + tl) * CO + co] = acc;
    }
}

// ============================ kernel 2: x0 = seq @ w_ih0^T + (b_ih0+b_hh0) ============================
// block tile: 128 (M) x 64 (N), K = 128 fully in smem. 256 threads, 8x4 per thread, FFMA2 inner.
#define PROJ_SMEM_BYTES ((128 * 132 + 128 * 64) * 4)
__global__ void proj_kernel(const float* __restrict__ w, const float* __restrict__ bi,
                            const float* __restrict__ bh) {
    extern __shared__ float sm[];
    float* As = sm;                 // [128][132] (padded)
    float* Ws = sm + 128 * 132;     // [k=128][n=64]
    int tid = threadIdx.x;
    int mt = blockIdx.x, nt = blockIdx.y;
    const float* Ab = g_seq + (size_t)mt * 128 * CO;
    for (int i = tid; i < 128 * 32; i += 256) {
        int row = i >> 5, c4 = i & 31;
        float4 v = reinterpret_cast<const float4*>(Ab)[(size_t)row * 32 + c4];
        float* d = As + row * 132 + c4 * 4;
        d[0] = v.x; d[1] = v.y; d[2] = v.z; d[3] = v.w;
    }
    for (int i = tid; i < 64 * 128; i += 256) {
        int n = i >> 7, k = i & 127;
        Ws[k * 64 + n] = w[(size_t)(nt * 64 + n) * CO + k];
    }
    __syncthreads();
    int ty = tid >> 4, tx = tid & 15;
    unsigned long long acc2[8][2];
#pragma unroll
    for (int i = 0; i < 8; i++) { acc2[i][0] = 0ull; acc2[i][1] = 0ull; }
#pragma unroll 2
    for (int k0 = 0; k0 < 128; k0 += 4) {
        float4 av[8];
#pragma unroll
        for (int m = 0; m < 8; m++)
            av[m] = *reinterpret_cast<const float4*>(As + (ty * 8 + m) * 132 + k0);
#pragma unroll
        for (int kk = 0; kk < 4; kk++) {
            ulonglong2 w2 = *reinterpret_cast<const ulonglong2*>(Ws + (k0 + kk) * 64 + tx * 4);
#pragma unroll
            for (int m = 0; m < 8; m++) {
                float a = (kk == 0) ? av[m].x : (kk == 1) ? av[m].y : (kk == 2) ? av[m].z : av[m].w;
                unsigned long long a2 = pack2(a, a);
                acc2[m][0] = fma2(a2, w2.x, acc2[m][0]);
                acc2[m][1] = fma2(a2, w2.y, acc2[m][1]);
            }
        }
    }
    int n0 = nt * 64 + tx * 4;
    float bb0 = bi[n0] + bh[n0], bb1 = bi[n0 + 1] + bh[n0 + 1];
    float bb2 = bi[n0 + 2] + bh[n0 + 2], bb3 = bi[n0 + 3] + bh[n0 + 3];
#pragma unroll
    for (int i = 0; i < 8; i++) {
        float4 o;
        unpack2(acc2[i][0], o.x, o.y);
        unpack2(acc2[i][1], o.z, o.w);
        o.x += bb0; o.y += bb1; o.z += bb2; o.w += bb3;
        *reinterpret_cast<float4*>(g_x0 + ((size_t)mt * 128 + ty * 8 + i) * Gg + n0) = o;
    }
}

// ============================ kernel 3: persistent 2-layer LSTM, cluster-of-4 ============================
// 32 clusters x 4 CTAs, 256 threads/CTA. Cluster owns 4 batch rows.
// CTA r owns gate rows {g*128 + r*32 + j}. Threads split the k-dim in half.
// Weights in smem (registers spill — measured R7/R8). FFMA2 inner loops.
// FUSED h0 pass: GEMM A (W_hh0.h0) and GEMM B part 1 (W_ih1.h0) share each loaded
// h0 register -> h broadcasts drop from 192 to 128 per thread per step.
// Both GEMMs computed unconditionally; only gtmp stores are guarded at t=0 / t=Tt.

__device__ __forceinline__ float tanh_fast(float x) {
    float y; asm("tanh.approx.f32 %0, %1;" : "=f"(y) : "f"(x)); return y;
}
__device__ __forceinline__ float sig_fast(float x) {
    return fmaf(tanh_fast(0.5f * x), 0.5f, 0.5f);
}

#define LSTM_SMEM_BYTES ((3 * 128 * 132 + 2048 + 2048) * 4)

__global__ void __cluster_dims__(4, 1, 1) __launch_bounds__(256, 1)
lstm_kernel(const float* __restrict__ whh0, const float* __restrict__ wih1,
            const float* __restrict__ whh1, const float* __restrict__ bih1,
            const float* __restrict__ bhh1) {
    extern __shared__ float sm[];
    float* w0   = sm;                       // W_hh0 slice [128 rows][132]
    float* w1   = w0 + 128 * 132;           // W_ih1 slice
    float* w2   = w1 + 128 * 132;           // W_hh1 slice
    float* hbuf = w2 + 128 * 132;           // [2 p][2 layer][4 bb][128 k]
    float* gtmp = hbuf + 2048;              // [2 layer][4 bb][2 half][128 row]

    int tid = threadIdx.x;
    int half = tid >> 7;                    // k-half for GEMM; cell index for elementwise
    int wt = tid & 127, q = wt >> 5, j = wt & 31;
    uint32_t rank; asm("mov.u32 %0, %%cluster_ctarank;" : "=r"(rank));
    int r = (int)rank;
    int b0 = (blockIdx.x >> 2) * 4;
    int lr = wt;                            // local weight row
    int rowg = (q << 7) + (r << 5) + j;     // global gate row

    // load weight slices
    for (int i = tid; i < 128 * 128; i += 256) {
        int rl = i >> 7, k = i & 127;
        int rg = ((rl >> 5) << 7) + (r << 5) + (rl & 31);
        w0[rl * 132 + k] = whh0[(size_t)rg * Hh + k];
        w1[rl * 132 + k] = wih1[(size_t)rg * Hh + k];
        w2[rl * 132 + k] = whh1[(size_t)rg * Hh + k];
    }
    for (int i = tid; i < 2048; i += 256) hbuf[i] = 0.f;

    float b1init = (half == 0) ? (bih1[rowg] + bhh1[rowg]) : 0.f;

    // elementwise role: (cell=half, batch=q, h index hl)
    int hl = (r << 5) + j;
    float cst = 0.f, pool = 0.f;

    float xn[4];
    if (half == 0) {
#pragma unroll
        for (int bb = 0; bb < 4; bb++)
            xn[bb] = g_x0[((size_t)(b0 + bb) * Tt) * Gg + rowg];
    }

    // precompute remote DSMEM base addresses for all 4 ranks
    uint32_t hb_la = (uint32_t)__cvta_generic_to_shared(hbuf);
    uint32_t rb[4];
#pragma unroll
    for (int rk = 0; rk < 4; rk++)
        asm("mapa.shared::cluster.u32 %0, %1, %2;" : "=r"(rb[rk]) : "r"(hb_la), "r"(rk));

    __syncthreads();
    asm volatile("barrier.cluster.arrive.aligned;" ::: "memory");
    asm volatile("barrier.cluster.wait.aligned;"   ::: "memory");

    const ulonglong2* wr0 = reinterpret_cast<const ulonglong2*>(w0 + lr * 132 + half * 64);
    const ulonglong2* wr1 = reinterpret_cast<const ulonglong2*>(w1 + lr * 132 + half * 64);
    const ulonglong2* wr2 = reinterpret_cast<const ulonglong2*>(w2 + lr * 132 + half * 64);

    int p = 0;
    for (int t = 0; t <= Tt; t++) {
        const float* hcur = hbuf + p * 1024 + half * 64;   // layer0 h base (+512 for layer1 h)
        unsigned long long accA[4], accB[4];
#pragma unroll
        for (int bb = 0; bb < 4; bb++) {
            accA[bb] = pack2(half == 0 ? xn[bb] : 0.f, 0.f);
            accB[bb] = pack2(b1init, 0.f);
        }
        // ---- fused h0 pass: accA += W_hh0 . h0 ; accB += W_ih1 . h0 (shared h loads)
#pragma unroll
        for (int kq = 0; kq < 16; kq++) {
            ulonglong2 wv0 = wr0[kq];
            ulonglong2 wv1 = wr1[kq];
#pragma unroll
            for (int bb = 0; bb < 4; bb++) {
                ulonglong2 hv = reinterpret_cast<const ulonglong2*>(hcur + bb * 128)[kq];
                accA[bb] = fma2(wv0.x, hv.x, accA[bb]);
                accA[bb] = fma2(wv0.y, hv.y, accA[bb]);
                accB[bb] = fma2(wv1.x, hv.x, accB[bb]);
                accB[bb] = fma2(wv1.y, hv.y, accB[bb]);
            }
        }
        // ---- h1 pass: accB += W_hh1 . h1
#pragma unroll
        for (int kq = 0; kq < 16; kq++) {
            ulonglong2 wv2 = wr2[kq];
#pragma unroll
            for (int bb = 0; bb < 4; bb++) {
                ulonglong2 hv = reinterpret_cast<const ulonglong2*>(hcur + 512 + bb * 128)[kq];
                accB[bb] = fma2(wv2.x, hv.x, accB[bb]);
                accB[bb] = fma2(wv2.y, hv.y, accB[bb]);
            }
        }
        if (t < Tt) {
#pragma unroll
            for (int bb = 0; bb < 4; bb++)
                gtmp[((0 + bb) * 2 + half) * 128 + lr] = sum2(accA[bb]);
        }
        if (t > 0) {
#pragma unroll
            for (int bb = 0; bb < 4; bb++)
                gtmp[((4 + bb) * 2 + half) * 128 + lr] = sum2(accB[bb]);
        }
        __syncthreads();
        // ---- elementwise: thread owns (cell=half, batch=q, h=hl)
        bool act = (half == 0) ? (t < Tt) : (t > 0);
        if (act) {
            int gb = (half * 4 + q) * 256;     // gtmp base for (layer, batch)
            float gv[4];
#pragma unroll
            for (int g = 0; g < 4; g++)
                gv[g] = gtmp[gb + (g << 5) + j] + gtmp[gb + 128 + (g << 5) + j];
            float cn = sig_fast(gv[1]) * cst + sig_fast(gv[0]) * tanh_fast(gv[2]);
            float hn = sig_fast(gv[3]) * tanh_fast(cn);
            cst = cn;
            if (half) pool += hn;
            uint32_t off = (uint32_t)((((p ^ 1) << 10) + (half << 9) + (q << 7) + hl) << 2);
#pragma unroll
            for (int rk = 0; rk < 4; rk++)
                asm volatile("st.shared::cluster.f32 [%0], %1;"
                             :: "r"(rb[rk] + off), "f"(hn) : "memory");
        }
        asm volatile("barrier.cluster.arrive.aligned;" ::: "memory");
        if (half == 0 && t + 1 < Tt) {
#pragma unroll
            for (int bb = 0; bb < 4; bb++)
                xn[bb] = g_x0[((size_t)(b0 + bb) * Tt + (t + 1)) * Gg + rowg];
        }
        asm volatile("barrier.cluster.wait.aligned;" ::: "memory");
        p ^= 1;
    }
    if (half == 1)
        g_pooled[(size_t)(b0 + q) * Hh + hl] = pool * (1.0f / 2048.0f);
}

// ============================ kernel 4: out[b] = pooled[b,:] . lin_w + lin_b ============================
__global__ void final_kernel(const float* __restrict__ lw, const float* __restrict__ lb,
                             float* __restrict__ out) {
    int b = threadIdx.x;
    float acc = lb[0];
#pragma unroll 8
    for (int h = 0; h < Hh; h++) acc += g_pooled[b * Hh + h] * lw[h];
    out[b] = acc;
}

// ============================ launch ============================
extern "C" void kernel_launch(void* const* d_in, const int* in_sizes, int n_in,
                              void* d_out, int out_size) {
    (void)in_sizes; (void)n_in; (void)out_size;
    const float* x      = (const float*)d_in[0];
    const float* conv_w = (const float*)d_in[1];
    const float* conv_b = (const float*)d_in[2];
    const float* w_ih0  = (const float*)d_in[3];
    const float* w_hh0  = (const float*)d_in[4];
    const float* b_ih0  = (const float*)d_in[5];
    const float* b_hh0  = (const float*)d_in[6];
    const float* w_ih1  = (const float*)d_in[7];
    const float* w_hh1  = (const float*)d_in[8];
    const float* b_ih1  = (const float*)d_in[9];
    const float* b_hh1  = (const float*)d_in[10];
    const float* lin_w  = (const float*)d_in[11];
    const float* lin_b  = (const float*)d_in[12];
    float* out = (float*)d_out;

    cudaFuncSetAttribute(proj_kernel, cudaFuncAttributeMaxDynamicSharedMemorySize, PROJ_SMEM_BYTES);
    cudaFuncSetAttribute(lstm_kernel, cudaFuncAttributeMaxDynamicSharedMemorySize, LSTM_SMEM_BYTES);

    conv_kernel<<<dim3(Tt / 128, Bsz), 256>>>(x, conv_w, conv_b);
    proj_kernel<<<dim3((Bsz * Tt) / 128, Gg / 64), 256, PROJ_SMEM_BYTES>>>(w_ih0, b_ih0, b_hh0);
    lstm_kernel<<<128, 256, LSTM_SMEM_BYTES>>>(w_hh0, w_ih1, w_hh1, b_ih1, b_hh1);
    final_kernel<<<1, 128>>>(lin_w, lin_b, out);
}

// round 10
// speedup vs baseline: 4.4224x; 1.0804x over previous
#include <cuda_runtime.h>
#include <cstdint>
#include <cstddef>

#define Bsz 128
#define Tt  2048
#define Cin 16
#define CO  128
#define Hh  128
#define Gg  512

// -------- scratch (no allocations allowed; __device__ globals are the sanctioned path) ------
__device__ float g_seq[(size_t)Bsz * Tt * CO];      // conv output, [b*T+t][co]
__device__ float g_x0 [(size_t)Bsz * Tt * Gg];      // layer-0 input projection, [b*T+t][g]
__device__ float g_pooled[Bsz * Hh];                // mean over t of h1

// ---------------- packed f32x2 helpers ----------------
__device__ __forceinline__ unsigned long long fma2(unsigned long long a, unsigned long long b,
                                                   unsigned long long c) {
    unsigned long long d;
    asm("fma.rn.f32x2 %0, %1, %2, %3;" : "=l"(d) : "l"(a), "l"(b), "l"(c));
    return d;
}
__device__ __forceinline__ unsigned long long pack2(float lo, float hi) {
    unsigned long long r;
    asm("mov.b64 %0, {%1, %2};" : "=l"(r) : "f"(lo), "f"(hi));
    return r;
}
__device__ __forceinline__ void unpack2(unsigned long long v, float& a, float& b) {
    asm("mov.b64 {%0, %1}, %2;" : "=f"(a), "=f"(b) : "l"(v));
}
__device__ __forceinline__ float sum2(unsigned long long v) {
    float a, b; unpack2(v, a, b); return a + b;
}
// expand packed bf16x2 (lo16 = w[k], hi16 = w[k+1]) into f32x2 {w[k], w[k+1]}
__device__ __forceinline__ unsigned long long bf2f2(uint32_t p) {
    uint32_t lo = p << 16;
    uint32_t hi = p & 0xFFFF0000u;
    unsigned long long r;
    asm("mov.b64 %0, {%1, %2};" : "=l"(r) : "r"(lo), "r"(hi));
    return r;
}
// pack two fp32 into bf16x2 with round-to-nearest: low16 = bf16(a), high16 = bf16(b)
__device__ __forceinline__ uint32_t f2bf2(float a, float b) {
    uint32_t r;
    asm("cvt.rn.bf16x2.f32 %0, %1, %2;" : "=r"(r) : "f"(b), "f"(a));
    return r;
}

// ============================ kernel 1: conv1d(k=3,pad=1) + LeakyReLU ============================
__global__ void conv_kernel(const float* __restrict__ x, const float* __restrict__ cw,
                            const float* __restrict__ cb) {
    __shared__ float xs[130 * 16];     // t0-1 .. t0+128
    __shared__ float wct[48 * 128];    // [(c*3+kk)][co]
    __shared__ float cbs[128];
    int tid = threadIdx.x;
    int b = blockIdx.y, t0 = blockIdx.x * 128;
    for (int i = tid; i < 130 * 16; i += 256) {
        int row = i >> 4, c = i & 15;
        int t = t0 - 1 + row;
        xs[i] = (t >= 0 && t < Tt) ? x[((size_t)b * Tt + t) * Cin + c] : 0.0f;
    }
    for (int i = tid; i < 48 * 128; i += 256) {
        int co = i / 48, rem = i % 48;          // rem = c*3 + kk
        wct[rem * 128 + co] = cw[i];
    }
    if (tid < 128) cbs[tid] = cb[tid];
    __syncthreads();
    for (int idx = tid; idx < 128 * 128; idx += 256) {
        int tl = idx >> 7, co = idx & 127;
        float acc = cbs[co];
#pragma unroll
        for (int c = 0; c < 16; c++)
#pragma unroll
            for (int kk = 0; kk < 3; kk++)
                acc += xs[(tl + kk) * 16 + c] * wct[(c * 3 + kk) * 128 + co];
        acc = acc >= 0.f ? acc : 0.01f * acc;
        g_seq[((size_t)b * Tt + t0 + tl) * CO + co] = acc;
    }
}

// ============================ kernel 2: x0 = seq @ w_ih0^T + (b_ih0+b_hh0) ============================
// block tile: 128 (M) x 64 (N), K = 128 fully in smem. 256 threads, 8x4 per thread, FFMA2 inner.
#define PROJ_SMEM_BYTES ((128 * 132 + 128 * 64) * 4)
__global__ void proj_kernel(const float* __restrict__ w, const float* __restrict__ bi,
                            const float* __restrict__ bh) {
    extern __shared__ float sm[];
    float* As = sm;                 // [128][132] (padded)
    float* Ws = sm + 128 * 132;     // [k=128][n=64]
    int tid = threadIdx.x;
    int mt = blockIdx.x, nt = blockIdx.y;
    const float* Ab = g_seq + (size_t)mt * 128 * CO;
    for (int i = tid; i < 128 * 32; i += 256) {
        int row = i >> 5, c4 = i & 31;
        float4 v = reinterpret_cast<const float4*>(Ab)[(size_t)row * 32 + c4];
        float* d = As + row * 132 + c4 * 4;
        d[0] = v.x; d[1] = v.y; d[2] = v.z; d[3] = v.w;
    }
    for (int i = tid; i < 64 * 128; i += 256) {
        int n = i >> 7, k = i & 127;
        Ws[k * 64 + n] = w[(size_t)(nt * 64 + n) * CO + k];
    }
    __syncthreads();
    int ty = tid >> 4, tx = tid & 15;
    unsigned long long acc2[8][2];
#pragma unroll
    for (int i = 0; i < 8; i++) { acc2[i][0] = 0ull; acc2[i][1] = 0ull; }
#pragma unroll 2
    for (int k0 = 0; k0 < 128; k0 += 4) {
        float4 av[8];
#pragma unroll
        for (int m = 0; m < 8; m++)
            av[m] = *reinterpret_cast<const float4*>(As + (ty * 8 + m) * 132 + k0);
#pragma unroll
        for (int kk = 0; kk < 4; kk++) {
            ulonglong2 w2 = *reinterpret_cast<const ulonglong2*>(Ws + (k0 + kk) * 64 + tx * 4);
#pragma unroll
            for (int m = 0; m < 8; m++) {
                float a = (kk == 0) ? av[m].x : (kk == 1) ? av[m].y : (kk == 2) ? av[m].z : av[m].w;
                unsigned long long a2 = pack2(a, a);
                acc2[m][0] = fma2(a2, w2.x, acc2[m][0]);
                acc2[m][1] = fma2(a2, w2.y, acc2[m][1]);
            }
        }
    }
    int n0 = nt * 64 + tx * 4;
    float bb0 = bi[n0] + bh[n0], bb1 = bi[n0 + 1] + bh[n0 + 1];
    float bb2 = bi[n0 + 2] + bh[n0 + 2], bb3 = bi[n0 + 3] + bh[n0 + 3];
#pragma unroll
    for (int i = 0; i < 8; i++) {
        float4 o;
        unpack2(acc2[i][0], o.x, o.y);
        unpack2(acc2[i][1], o.z, o.w);
        o.x += bb0; o.y += bb1; o.z += bb2; o.w += bb3;
        *reinterpret_cast<float4*>(g_x0 + ((size_t)mt * 128 + ty * 8 + i) * Gg + n0) = o;
    }
}

// ============================ kernel 3: persistent 2-layer LSTM, cluster-of-4 ============================
// 32 clusters x 4 CTAs, 256 threads/CTA. Cluster owns 4 batch rows.
// CTA r owns gate rows {g*128 + r*32 + j}. Threads split the k-dim in half.
// Recurrent weights stored in smem as packed bf16x2 (halves weight crossbar traffic);
// expansion to f32x2 via 2 ALU ops per pair (separate pipe from FMA). fp32 accumulate.
// FUSED h0 pass: W_hh0.h0 and W_ih1.h0 share each loaded h register.
// Both GEMMs computed unconditionally; only gtmp stores are guarded at t=0 / t=Tt.

__device__ __forceinline__ float tanh_fast(float x) {
    float y; asm("tanh.approx.f32 %0, %1;" : "=f"(y) : "f"(x)); return y;
}
__device__ __forceinline__ float sig_fast(float x) {
    return fmaf(tanh_fast(0.5f * x), 0.5f, 0.5f);
}

// bf16 weight rows: 64 pairs + 4 pad = 68 uint32 per row (68 mod 32 = 4 -> optimal LDS.128 phases)
#define WROW 68
#define LSTM_SMEM_BYTES ((3 * 128 * WROW + 2048 + 2048) * 4)

__global__ void __cluster_dims__(4, 1, 1) __launch_bounds__(256, 1)
lstm_kernel(const float* __restrict__ whh0, const float* __restrict__ wih1,
            const float* __restrict__ whh1, const float* __restrict__ bih1,
            const float* __restrict__ bhh1) {
    extern __shared__ float sm[];
    uint32_t* w0 = reinterpret_cast<uint32_t*>(sm);          // W_hh0 slice [128 rows][WROW]
    uint32_t* w1 = w0 + 128 * WROW;                          // W_ih1 slice
    uint32_t* w2 = w1 + 128 * WROW;                          // W_hh1 slice
    float* hbuf = sm + 3 * 128 * WROW;                       // [2 p][2 layer][4 bb][128 k]
    float* gtmp = hbuf + 2048;                               // [2 layer][4 bb][2 half][128 row]

    int tid = threadIdx.x;
    int half = tid >> 7;                    // k-half for GEMM; cell index for elementwise
    int wt = tid & 127, q = wt >> 5, j = wt & 31;
    uint32_t rank; asm("mov.u32 %0, %%cluster_ctarank;" : "=r"(rank));
    int r = (int)rank;
    int b0 = (blockIdx.x >> 2) * 4;
    int lr = wt;                            // local weight row
    int rowg = (q << 7) + (r << 5) + j;     // global gate row

    // load weight slices, converting fp32 -> packed bf16x2 (low16 = even k)
    for (int i = tid; i < 128 * 64; i += 256) {
        int rl = i >> 6, c = i & 63;        // row, pair index
        int rg = ((rl >> 5) << 7) + (r << 5) + (rl & 31);
        size_t gb = (size_t)rg * Hh + 2 * c;
        w0[rl * WROW + c] = f2bf2(whh0[gb], whh0[gb + 1]);
        w1[rl * WROW + c] = f2bf2(wih1[gb], wih1[gb + 1]);
        w2[rl * WROW + c] = f2bf2(whh1[gb], whh1[gb + 1]);
    }
    for (int i = tid; i < 2048; i += 256) hbuf[i] = 0.f;

    float b1init = (half == 0) ? (bih1[rowg] + bhh1[rowg]) : 0.f;

    // elementwise role: (cell=half, batch=q, h index hl)
    int hl = (r << 5) + j;
    float cst = 0.f, pool = 0.f;

    float xn[4];
    if (half == 0) {
#pragma unroll
        for (int bb = 0; bb < 4; bb++)
            xn[bb] = g_x0[((size_t)(b0 + bb) * Tt) * Gg + rowg];
    }

    // precompute remote DSMEM base addresses for all 4 ranks
    uint32_t hb_la = (uint32_t)__cvta_generic_to_shared(hbuf);
    uint32_t rb[4];
#pragma unroll
    for (int rk = 0; rk < 4; rk++)
        asm("mapa.shared::cluster.u32 %0, %1, %2;" : "=r"(rb[rk]) : "r"(hb_la), "r"(rk));

    __syncthreads();
    asm volatile("barrier.cluster.arrive.aligned;" ::: "memory");
    asm volatile("barrier.cluster.wait.aligned;"   ::: "memory");

    // this thread's weight row-half: 32 pairs = 8 uint4 loads per matrix
    const uint4* wr0 = reinterpret_cast<const uint4*>(w0 + lr * WROW + half * 32);
    const uint4* wr1 = reinterpret_cast<const uint4*>(w1 + lr * WROW + half * 32);
    const uint4* wr2 = reinterpret_cast<const uint4*>(w2 + lr * WROW + half * 32);

    int p = 0;
    for (int t = 0; t <= Tt; t++) {
        const float* hcur = hbuf + p * 1024 + half * 64;   // layer0 h base (+512 for layer1 h)
        unsigned long long accA[4], accB[4];
#pragma unroll
        for (int bb = 0; bb < 4; bb++) {
            accA[bb] = pack2(half == 0 ? xn[bb] : 0.f, 0.f);
            accB[bb] = pack2(b1init, 0.f);
        }
        // ---- fused h0 pass: accA += W_hh0 . h0 ; accB += W_ih1 . h0 (shared h loads)
        //      8 iters x 8 k each
#pragma unroll
        for (int kq = 0; kq < 8; kq++) {
            uint4 p0 = wr0[kq], p1 = wr1[kq];
            unsigned long long w0a = bf2f2(p0.x), w0b = bf2f2(p0.y),
                               w0c = bf2f2(p0.z), w0d = bf2f2(p0.w);
            unsigned long long w1a = bf2f2(p1.x), w1b = bf2f2(p1.y),
                               w1c = bf2f2(p1.z), w1d = bf2f2(p1.w);
#pragma unroll
            for (int bb = 0; bb < 4; bb++) {
                const ulonglong2* hp = reinterpret_cast<const ulonglong2*>(hcur + bb * 128) + kq * 2;
                ulonglong2 h01 = hp[0], h23 = hp[1];
                accA[bb] = fma2(w0a, h01.x, accA[bb]);
                accA[bb] = fma2(w0b, h01.y, accA[bb]);
                accA[bb] = fma2(w0c, h23.x, accA[bb]);
                accA[bb] = fma2(w0d, h23.y, accA[bb]);
                accB[bb] = fma2(w1a, h01.x, accB[bb]);
                accB[bb] = fma2(w1b, h01.y, accB[bb]);
                accB[bb] = fma2(w1c, h23.x, accB[bb]);
                accB[bb] = fma2(w1d, h23.y, accB[bb]);
            }
        }
        // ---- h1 pass: accB += W_hh1 . h1
#pragma unroll
        for (int kq = 0; kq < 8; kq++) {
            uint4 p2 = wr2[kq];
            unsigned long long w2a = bf2f2(p2.x), w2b = bf2f2(p2.y),
                               w2c = bf2f2(p2.z), w2d = bf2f2(p2.w);
#pragma unroll
            for (int bb = 0; bb < 4; bb++) {
                const ulonglong2* hp =
                    reinterpret_cast<const ulonglong2*>(hcur + 512 + bb * 128) + kq * 2;
                ulonglong2 h01 = hp[0], h23 = hp[1];
                accB[bb] = fma2(w2a, h01.x, accB[bb]);
                accB[bb] = fma2(w2b, h01.y, accB[bb]);
                accB[bb] = fma2(w2c, h23.x, accB[bb]);
                accB[bb] = fma2(w2d, h23.y, accB[bb]);
            }
        }
        if (t < Tt) {
#pragma unroll
            for (int bb = 0; bb < 4; bb++)
                gtmp[((0 + bb) * 2 + half) * 128 + lr] = sum2(accA[bb]);
        }
        if (t > 0) {
#pragma unroll
            for (int bb = 0; bb < 4; bb++)
                gtmp[((4 + bb) * 2 + half) * 128 + lr] = sum2(accB[bb]);
        }
        __syncthreads();
        // ---- elementwise: thread owns (cell=half, batch=q, h=hl)
        bool act = (half == 0) ? (t < Tt) : (t > 0);
        if (act) {
            int gb = (half * 4 + q) * 256;     // gtmp base for (layer, batch)
            float gv[4];
#pragma unroll
            for (int g = 0; g < 4; g++)
                gv[g] = gtmp[gb + (g << 5) + j] + gtmp[gb + 128 + (g << 5) + j];
            float cn = sig_fast(gv[1]) * cst + sig_fast(gv[0]) * tanh_fast(gv[2]);
            float hn = sig_fast(gv[3]) * tanh_fast(cn);
            cst = cn;
            if (half) pool += hn;
            uint32_t off = (uint32_t)((((p ^ 1) << 10) + (half << 9) + (q << 7) + hl) << 2);
#pragma unroll
            for (int rk = 0; rk < 4; rk++)
                asm volatile("st.shared::cluster.f32 [%0], %1;"
                             :: "r"(rb[rk] + off), "f"(hn) : "memory");
        }
        asm volatile("barrier.cluster.arrive.aligned;" ::: "memory");
        if (half == 0 && t + 1 < Tt) {
#pragma unroll
            for (int bb = 0; bb < 4; bb++)
                xn[bb] = g_x0[((size_t)(b0 + bb) * Tt + (t + 1)) * Gg + rowg];
        }
        asm volatile("barrier.cluster.wait.aligned;" ::: "memory");
        p ^= 1;
    }
    if (half == 1)
        g_pooled[(size_t)(b0 + q) * Hh + hl] = pool * (1.0f / 2048.0f);
}

// ============================ kernel 4: out[b] = pooled[b,:] . lin_w + lin_b ============================
__global__ void final_kernel(const float* __restrict__ lw, const float* __restrict__ lb,
                             float* __restrict__ out) {
    int b = threadIdx.x;
    float acc = lb[0];
#pragma unroll 8
    for (int h = 0; h < Hh; h++) acc += g_pooled[b * Hh + h] * lw[h];
    out[b] = acc;
}

// ============================ launch ============================
extern "C" void kernel_launch(void* const* d_in, const int* in_sizes, int n_in,
                              void* d_out, int out_size) {
    (void)in_sizes; (void)n_in; (void)out_size;
    const float* x      = (const float*)d_in[0];
    const float* conv_w = (const float*)d_in[1];
    const float* conv_b = (const float*)d_in[2];
    const float* w_ih0  = (const float*)d_in[3];
    const float* w_hh0  = (const float*)d_in[4];
    const float* b_ih0  = (const float*)d_in[5];
    const float* b_hh0  = (const float*)d_in[6];
    const float* w_ih1  = (const float*)d_in[7];
    const float* w_hh1  = (const float*)d_in[8];
    const float* b_ih1  = (const float*)d_in[9];
    const float* b_hh1  = (const float*)d_in[10];
    const float* lin_w  = (const float*)d_in[11];
    const float* lin_b  = (const float*)d_in[12];
    float* out = (float*)d_out;

    cudaFuncSetAttribute(proj_kernel, cudaFuncAttributeMaxDynamicSharedMemorySize, PROJ_SMEM_BYTES);
    cudaFuncSetAttribute(lstm_kernel, cudaFuncAttributeMaxDynamicSharedMemorySize, LSTM_SMEM_BYTES);

    conv_kernel<<<dim3(Tt / 128, Bsz), 256>>>(x, conv_w, conv_b);
    proj_kernel<<<dim3((Bsz * Tt) / 128, Gg / 64), 256, PROJ_SMEM_BYTES>>>(w_ih0, b_ih0, b_hh0);
    lstm_kernel<<<128, 256, LSTM_SMEM_BYTES>>>(w_hh0, w_ih1, w_hh1, b_ih1, b_hh1);
    final_kernel<<<1, 128>>>(lin_w, lin_b, out);
}